// round 15
// baseline (speedup 1.0000x reference)
#include <cuda_runtime.h>

#define BB 8
#define LL 128
#define HH 768
#define HV (HH / 4)       // 192 float4 columns
#define NLAB 3
#define KT 8              // keys per gemm block
#define NKT (LL / KT)     // 16 k-tiles per batch

// scratch (allocation-free rule: __device__ globals)
__device__ __align__(16) float g_u[BB * LL * LL];   // u scores (non-hz rows only)
__device__ __align__(16) float g_o[BB * LL * HH];

// ---------------------------------------------------------------------------
// Kernel 1: per-batch key GEMM. U[b,q,k] = dot(hidden[b,q], Wk[kvidx[b,k]])/sqrt(H)
// grid = BB*NKT = 128 blocks, 256 threads. Keys read ONCE per batch (was 128x).
// Key rows loaded straight into registers (warp-exclusive) — no smem staging.
// ---------------------------------------------------------------------------
__global__ __launch_bounds__(256) void gemm_k(
    const float* __restrict__ seq,    // [B,L,H]
    const float* __restrict__ Wk,     // [VOCAB,H]
    const int*   __restrict__ valid,  // [B,L]
    const int*   __restrict__ kvidx,  // [B,L]
    const int*   __restrict__ asp)    // [B,L]
{
    const int b    = blockIdx.x / NKT;
    const int kt   = blockIdx.x % NKT;
    const int tid  = threadIdx.x;
    const int lane = tid & 31;
    const int wid  = tid >> 5;        // 0..7, warp w owns key kt*8+w

    __shared__ __align__(16) float4 shid[8][HV];    // 24 KB
    __shared__ int s_srcmap[LL];
    __shared__ int s_qlist[LL];
    __shared__ int wsum[4];
    __shared__ int s_nq;

    if (tid == 0) s_nq = 0;

    // ---- stable-partition scan ----
    int v = 0;
    unsigned mask = 0;
    if (tid < LL) v = valid[b * LL + tid];
    if (wid < 4) {
        mask = __ballot_sync(0xFFFFFFFFu, v != 0);
        if (lane == 0) wsum[wid] = __popc(mask);
    }
    __syncthreads();
    const int count = wsum[0] + wsum[1] + wsum[2] + wsum[3];
    if (wid < 4 && v) {
        int pref = __popc(mask & ((1u << lane) - 1u));
        if (wid > 0) pref += wsum[0];
        if (wid > 1) pref += wsum[1];
        if (wid > 2) pref += wsum[2];
        s_srcmap[pref] = tid;          // src token for q = pref
    }
    // non-hz q list (aspect is binary -> no scale needed)
    if (tid < LL && tid < count && asp[b * LL + tid] != 0) {
        int slot = atomicAdd(&s_nq, 1);
        s_qlist[slot] = tid;
    }

    // ---- load this warp's key row directly into registers ----
    const int kidx = kvidx[b * LL + kt * KT + wid];
    const float4* krow = (const float4*)(Wk + (size_t)kidx * HH);
    float4 kreg[6];
    #pragma unroll
    for (int i = 0; i < 6; ++i) kreg[i] = __ldg(krow + lane + 32 * i);
    __syncthreads();

    const int nq = s_nq;
    const float invscale = 1.0f / 27.712812921102035f;  // 1/sqrt(768)
    const float4* seqv = (const float4*)seq;

    for (int q0 = 0; q0 < nq; q0 += 8) {
        const int nch = (nq - q0 < 8) ? (nq - q0) : 8;
        for (int idx = tid; idx < nch * HV; idx += 256) {
            int j = idx / HV, i = idx - j * HV;
            int q = s_qlist[q0 + j];
            shid[j][i] = __ldg(seqv + (size_t)(b * LL + s_srcmap[q]) * HV + i);
        }
        __syncthreads();

        float s[8];
        #pragma unroll
        for (int j = 0; j < 8; ++j) s[j] = 0.f;
        #pragma unroll
        for (int j = 0; j < 8; ++j) {
            #pragma unroll
            for (int i = 0; i < 6; ++i) {
                float4 h = shid[j][lane + 32 * i];
                s[j] += h.x * kreg[i].x + h.y * kreg[i].y
                      + h.z * kreg[i].z + h.w * kreg[i].w;
            }
        }
        // 8 interleaved butterfly reductions (independent chains)
        #pragma unroll
        for (int off = 16; off; off >>= 1) {
            #pragma unroll
            for (int j = 0; j < 8; ++j)
                s[j] += __shfl_xor_sync(0xFFFFFFFFu, s[j], off);
        }
        if (lane == 0) {
            for (int j = 0; j < nch; ++j) {
                int q = s_qlist[q0 + j];
                g_u[((size_t)b * LL + q) * LL + kt * KT + wid] =
                    (kidx != 0) ? s[j] * invscale : 0.f;  // padding key -> u=0
            }
        }
        __syncthreads();               // protect shid reuse
    }
}

// ---------------------------------------------------------------------------
// Kernel 2: softmax + compaction + value gather. grid = 1024, 192 threads.
// ---------------------------------------------------------------------------
__global__ __launch_bounds__(192) void attn2_k(
    const float* __restrict__ Wv,     // [FEAT_VOCAB,H]
    const int*   __restrict__ valid,  // [B,L]
    const int*   __restrict__ feat,   // [B,L,L]
    const int*   __restrict__ posm,   // [B,L,L]
    const int*   __restrict__ asp)    // [B,L]
{
    const int bq   = blockIdx.x;
    const int b    = bq / LL;
    const int q    = bq % LL;
    const int tid  = threadIdx.x;
    const int lane = tid & 31;
    const int wid  = tid >> 5;        // 0..5

    __shared__ float cp_p[LL];
    __shared__ int   cp_i[LL];
    __shared__ int   fidx[LL];
    __shared__ int   wsum[4];
    __shared__ int   s_nact;
    __shared__ float warp_red[6];
    __shared__ float s_dsum;

    if (tid == 0) s_nact = 0;

    int v = 0;
    unsigned mask = 0;
    if (tid < LL) v = valid[b * LL + tid];
    if (wid < 4) {
        mask = __ballot_sync(0xFFFFFFFFu, v != 0);
        if (lane == 0) wsum[wid] = __popc(mask);
    }
    if (tid < LL) fidx[tid] = feat[(size_t)bq * LL + tid];
    __syncthreads();
    const int count = wsum[0] + wsum[1] + wsum[2] + wsum[3];
    const bool hz = (q >= count) || (asp[b * LL + q] == 0);

    // ---- delta = exp(u)*pos ----
    float dloc = 0.f;
    if (tid < LL) {
        int pm = posm[(size_t)bq * LL + tid];
        if (pm != 0) {
            float u = hz ? 0.f : g_u[(size_t)bq * LL + tid];
            dloc = expf(u);
        }
    }
    float r = dloc;
    #pragma unroll
    for (int off = 16; off; off >>= 1) r += __shfl_xor_sync(0xFFFFFFFFu, r, off);
    if (lane == 0) warp_red[wid] = r;
    __syncthreads();
    if (tid == 0) {
        float t = 0.f;
        #pragma unroll
        for (int w = 0; w < 6; ++w) t += warp_red[w];
        s_dsum = t;
    }
    __syncthreads();
    const float inv = 1.f / (s_dsum + 1e-10f);

    if (tid < LL && dloc != 0.f) {
        int idx = fidx[tid];
        if (idx != 0) {
            int slot = atomicAdd(&s_nact, 1);
            cp_p[slot] = dloc * inv;
            cp_i[slot] = idx;
        }
    }
    __syncthreads();
    const int nact = s_nact;

    // ---- o[b,q,:] = sum_m p_m * Wv[idx_m,:] ----
    float4 acc = make_float4(0.f, 0.f, 0.f, 0.f);
    const float4* WvV = (const float4*)Wv;
    #pragma unroll 16
    for (int m = 0; m < nact; ++m) {
        float  pk = cp_p[m];
        float4 vv = __ldg(WvV + (size_t)cp_i[m] * HV + tid);
        acc.x += pk * vv.x; acc.y += pk * vv.y;
        acc.z += pk * vv.z; acc.w += pk * vv.w;
    }
    ((float4*)(g_o + (size_t)bq * HH))[tid] = acc;
}

// ---------------------------------------------------------------------------
// Kernel 3: fused reduce + head (R13's, measured best). grid = 8, 768 thr.
// ---------------------------------------------------------------------------
__global__ __launch_bounds__(768) void reduce_head_k(
    const float* __restrict__ pooled,  // [B,H]
    const float* __restrict__ Wd,      // [3,2H]
    const float* __restrict__ bd,      // [3]
    float*       __restrict__ out)     // [B,3]
{
    const int b   = blockIdx.x;
    const int t   = threadIdx.x;       // 0..767
    const int col = t % 192;
    const int seg = t / 192;           // 0..3: rows seg*32..seg*32+31

    __shared__ __align__(16) float4 s_s[4][192];
    __shared__ __align__(16) float4 s_c[4][192];
    __shared__ float wred[6][NLAB];

    const float4* ob = (const float4*)g_o + ((size_t)b * LL + seg * 32) * HV + col;

    float4 s = make_float4(0.f, 0.f, 0.f, 0.f);
    float4 c = make_float4(0.f, 0.f, 0.f, 0.f);
    #pragma unroll 1
    for (int r0 = 0; r0 < 32; r0 += 16) {
        float4 vv[16];
        #pragma unroll
        for (int j = 0; j < 16; ++j)
            vv[j] = ob[(size_t)(r0 + j) * HV];
        #pragma unroll
        for (int j = 0; j < 16; ++j) {
            s.x += vv[j].x; s.y += vv[j].y; s.z += vv[j].z; s.w += vv[j].w;
            c.x += (vv[j].x != 0.f) ? 1.f : 0.f;
            c.y += (vv[j].y != 0.f) ? 1.f : 0.f;
            c.z += (vv[j].z != 0.f) ? 1.f : 0.f;
            c.w += (vv[j].w != 0.f) ? 1.f : 0.f;
        }
    }
    s_s[seg][col] = s;
    s_c[seg][col] = c;
    __syncthreads();

    if (t < 192) {
        const int lane = t & 31;
        const int wid  = t >> 5;

        float4 ss = s_s[0][t], cc = s_c[0][t];
        #pragma unroll
        for (int g = 1; g < 4; ++g) {
            float4 ps = s_s[g][t], pc = s_c[g][t];
            ss.x += ps.x; ss.y += ps.y; ss.z += ps.z; ss.w += ps.w;
            cc.x += pc.x; cc.y += pc.y; cc.z += pc.z; cc.w += pc.w;
        }
        float4 avg = make_float4(ss.x / cc.x, ss.y / cc.y, ss.z / cc.z, ss.w / cc.w);
        float4 pv  = ((const float4*)pooled)[b * HV + t];

        #pragma unroll
        for (int n = 0; n < NLAB; ++n) {
            float4 w0 = ((const float4*)(Wd + n * 2 * HH))[t];
            float4 w1 = ((const float4*)(Wd + n * 2 * HH + HH))[t];
            float x = pv.x * w0.x + pv.y * w0.y + pv.z * w0.z + pv.w * w0.w
                    + avg.x * w1.x + avg.y * w1.y + avg.z * w1.z + avg.w * w1.w;
            #pragma unroll
            for (int off = 16; off; off >>= 1)
                x += __shfl_xor_sync(0xFFFFFFFFu, x, off);
            if (lane == 0) wred[wid][n] = x;
        }
    }
    __syncthreads();
    if (t < NLAB) {
        float tot = bd[t];
        #pragma unroll
        for (int w = 0; w < 6; ++w) tot += wred[w][t];
        out[b * NLAB + t] = tot;
    }
}

extern "C" void kernel_launch(void* const* d_in, const int* in_sizes, int n_in,
                              void* d_out, int out_size) {
    const float* seq    = (const float*)d_in[0];
    const float* pooled = (const float*)d_in[1];
    const float* Wk     = (const float*)d_in[2];
    const float* Wv     = (const float*)d_in[3];
    const float* Wd     = (const float*)d_in[4];
    const float* bd     = (const float*)d_in[5];
    const int*   valid  = (const int*)d_in[6];
    const int*   kvidx  = (const int*)d_in[7];
    const int*   feat   = (const int*)d_in[8];
    const int*   posm   = (const int*)d_in[9];
    const int*   asp    = (const int*)d_in[10];

    gemm_k<<<BB * NKT, 256>>>(seq, Wk, valid, kvidx, asp);
    attn2_k<<<BB * LL, 192>>>(Wv, valid, feat, posm, asp);
    reduce_head_k<<<BB, 768>>>(pooled, Wd, bd, (float*)d_out);
}

// round 16
// speedup vs baseline: 1.1099x; 1.1099x over previous
#include <cuda_runtime.h>

#define BB 8
#define LL 128
#define HH 768
#define HV (HH / 4)       // 192 float4 columns
#define NLAB 3
#define KT 8              // keys per gemm block
#define NKT (LL / KT)     // 16 k-tiles per batch
#define QC 8              // q rows per gemm block
#define NQC (LL / QC)     // 16 q-chunks (worst case)

// scratch (allocation-free rule: __device__ globals)
__device__ __align__(16) float g_u[BB * LL * LL];   // u scores (non-hz rows only)
__device__ __align__(16) float g_o[BB * LL * HH];

// ---------------------------------------------------------------------------
// Kernel 1: one-shot key GEMM tile. block = (b, kt, ch): 8 keys x 8 q rows.
// grid = BB*NKT*NQC = 2048; blocks with ch*QC >= nq exit after the scan.
// ---------------------------------------------------------------------------
__global__ __launch_bounds__(256) void gemm_k(
    const float* __restrict__ seq,    // [B,L,H]
    const float* __restrict__ Wk,     // [VOCAB,H]
    const int*   __restrict__ valid,  // [B,L]
    const int*   __restrict__ kvidx,  // [B,L]
    const int*   __restrict__ asp)    // [B,L]
{
    const int blk  = blockIdx.x;
    const int b    = blk / (NKT * NQC);
    const int kt   = (blk / NQC) % NKT;
    const int ch   = blk % NQC;
    const int tid  = threadIdx.x;
    const int lane = tid & 31;
    const int wid  = tid >> 5;        // 0..7, warp w owns key kt*8+w

    __shared__ __align__(16) float4 shid[QC][HV];   // 24 KB
    __shared__ int s_srcmap[LL];
    __shared__ int s_qsel[QC];
    __shared__ int wsum[4];
    __shared__ int asum[4];

    // ---- deterministic scans (identical in every block) ----
    int v = 0, a = 0;
    unsigned vm = 0;
    if (tid < LL) {
        v = valid[b * LL + tid];
        a = asp[b * LL + tid];
    }
    if (wid < 4) {
        vm = __ballot_sync(0xFFFFFFFFu, v != 0);
        if (lane == 0) wsum[wid] = __popc(vm);
    }
    __syncthreads();
    const int count = wsum[0] + wsum[1] + wsum[2] + wsum[3];
    if (wid < 4 && v) {
        int pref = __popc(vm & ((1u << lane) - 1u));
        if (wid > 0) pref += wsum[0];
        if (wid > 1) pref += wsum[1];
        if (wid > 2) pref += wsum[2];
        s_srcmap[pref] = tid;          // src token for q = pref
    }
    // non-hz q compaction: ballot/prefix (ascending q, deterministic)
    int pred = 0;
    unsigned am = 0;
    if (wid < 4) {
        pred = (tid < count) && (a != 0);
        am = __ballot_sync(0xFFFFFFFFu, pred);
        if (lane == 0) asum[wid] = __popc(am);
    }
    __syncthreads();
    const int nq = asum[0] + asum[1] + asum[2] + asum[3];
    if (ch * QC >= nq) return;         // this chunk has no work
    if (wid < 4 && pred) {
        int pos = __popc(am & ((1u << lane) - 1u));
        if (wid > 0) pos += asum[0];
        if (wid > 1) pos += asum[1];
        if (wid > 2) pos += asum[2];
        int rel = pos - ch * QC;
        if (rel >= 0 && rel < QC) s_qsel[rel] = tid;   // q index for slot rel
    }
    __syncthreads();

    const int nch = (nq - ch * QC < QC) ? (nq - ch * QC) : QC;

    // ---- load this warp's key row directly into registers ----
    const int kidx = kvidx[b * LL + kt * KT + wid];
    const float4* krow = (const float4*)(Wk + (size_t)kidx * HH);
    float4 kreg[6];
    #pragma unroll
    for (int i = 0; i < 6; ++i) kreg[i] = __ldg(krow + lane + 32 * i);

    // ---- stage the chunk's hidden rows (one shot) ----
    const float4* seqv = (const float4*)seq;
    for (int idx = tid; idx < nch * HV; idx += 256) {
        int j = idx / HV, i = idx - j * HV;
        shid[j][i] = __ldg(seqv + (size_t)(b * LL + s_srcmap[s_qsel[j]]) * HV + i);
    }
    __syncthreads();

    // ---- 8x8 dot tile ----
    float s[QC];
    #pragma unroll
    for (int j = 0; j < QC; ++j) s[j] = 0.f;
    #pragma unroll
    for (int j = 0; j < QC; ++j) {
        #pragma unroll
        for (int i = 0; i < 6; ++i) {
            float4 h = shid[j][lane + 32 * i];
            s[j] += h.x * kreg[i].x + h.y * kreg[i].y
                  + h.z * kreg[i].z + h.w * kreg[i].w;
        }
    }
    #pragma unroll
    for (int off = 16; off; off >>= 1) {
        #pragma unroll
        for (int j = 0; j < QC; ++j)
            s[j] += __shfl_xor_sync(0xFFFFFFFFu, s[j], off);
    }
    const float invscale = 1.0f / 27.712812921102035f;  // 1/sqrt(768)
    if (lane == 0) {
        #pragma unroll
        for (int j = 0; j < QC; ++j) {
            if (j < nch) {
                int q = s_qsel[j];
                g_u[((size_t)b * LL + q) * LL + kt * KT + wid] =
                    (kidx != 0) ? s[j] * invscale : 0.f;  // padding key -> u=0
            }
        }
    }
}

// ---------------------------------------------------------------------------
// Kernel 2: softmax + compaction + value gather. grid = 1024, 192 threads.
// ---------------------------------------------------------------------------
__global__ __launch_bounds__(192) void attn2_k(
    const float* __restrict__ Wv,     // [FEAT_VOCAB,H]
    const int*   __restrict__ valid,  // [B,L]
    const int*   __restrict__ feat,   // [B,L,L]
    const int*   __restrict__ posm,   // [B,L,L]
    const int*   __restrict__ asp)    // [B,L]
{
    const int bq   = blockIdx.x;
    const int b    = bq / LL;
    const int q    = bq % LL;
    const int tid  = threadIdx.x;
    const int lane = tid & 31;
    const int wid  = tid >> 5;        // 0..5

    __shared__ float cp_p[LL];
    __shared__ int   cp_i[LL];
    __shared__ int   fidx[LL];
    __shared__ int   wsum[4];
    __shared__ int   s_nact;
    __shared__ float warp_red[6];
    __shared__ float s_dsum;

    if (tid == 0) s_nact = 0;

    int v = 0;
    unsigned mask = 0;
    if (tid < LL) v = valid[b * LL + tid];
    if (wid < 4) {
        mask = __ballot_sync(0xFFFFFFFFu, v != 0);
        if (lane == 0) wsum[wid] = __popc(mask);
    }
    if (tid < LL) fidx[tid] = feat[(size_t)bq * LL + tid];
    __syncthreads();
    const int count = wsum[0] + wsum[1] + wsum[2] + wsum[3];
    const bool hz = (q >= count) || (asp[b * LL + q] == 0);

    // ---- delta = exp(u)*pos ----
    float dloc = 0.f;
    if (tid < LL) {
        int pm = posm[(size_t)bq * LL + tid];
        if (pm != 0) {
            float u = hz ? 0.f : g_u[(size_t)bq * LL + tid];
            dloc = expf(u);
        }
    }
    float r = dloc;
    #pragma unroll
    for (int off = 16; off; off >>= 1) r += __shfl_xor_sync(0xFFFFFFFFu, r, off);
    if (lane == 0) warp_red[wid] = r;
    __syncthreads();
    if (tid == 0) {
        float t = 0.f;
        #pragma unroll
        for (int w = 0; w < 6; ++w) t += warp_red[w];
        s_dsum = t;
    }
    __syncthreads();
    const float inv = 1.f / (s_dsum + 1e-10f);

    if (tid < LL && dloc != 0.f) {
        int idx = fidx[tid];
        if (idx != 0) {
            int slot = atomicAdd(&s_nact, 1);
            cp_p[slot] = dloc * inv;
            cp_i[slot] = idx;
        }
    }
    __syncthreads();
    const int nact = s_nact;

    // ---- o[b,q,:] = sum_m p_m * Wv[idx_m,:] ----
    float4 acc = make_float4(0.f, 0.f, 0.f, 0.f);
    const float4* WvV = (const float4*)Wv;
    #pragma unroll 16
    for (int m = 0; m < nact; ++m) {
        float  pk = cp_p[m];
        float4 vv = __ldg(WvV + (size_t)cp_i[m] * HV + tid);
        acc.x += pk * vv.x; acc.y += pk * vv.y;
        acc.z += pk * vv.z; acc.w += pk * vv.w;
    }
    ((float4*)(g_o + (size_t)bq * HH))[tid] = acc;
}

// ---------------------------------------------------------------------------
// Kernel 3: fused reduce + head (R13's, measured best). grid = 8, 768 thr.
// ---------------------------------------------------------------------------
__global__ __launch_bounds__(768) void reduce_head_k(
    const float* __restrict__ pooled,  // [B,H]
    const float* __restrict__ Wd,      // [3,2H]
    const float* __restrict__ bd,      // [3]
    float*       __restrict__ out)     // [B,3]
{
    const int b   = blockIdx.x;
    const int t   = threadIdx.x;       // 0..767
    const int col = t % 192;
    const int seg = t / 192;           // 0..3: rows seg*32..seg*32+31

    __shared__ __align__(16) float4 s_s[4][192];
    __shared__ __align__(16) float4 s_c[4][192];
    __shared__ float wred[6][NLAB];

    const float4* ob = (const float4*)g_o + ((size_t)b * LL + seg * 32) * HV + col;

    float4 s = make_float4(0.f, 0.f, 0.f, 0.f);
    float4 c = make_float4(0.f, 0.f, 0.f, 0.f);
    #pragma unroll 1
    for (int r0 = 0; r0 < 32; r0 += 16) {
        float4 vv[16];
        #pragma unroll
        for (int j = 0; j < 16; ++j)
            vv[j] = ob[(size_t)(r0 + j) * HV];
        #pragma unroll
        for (int j = 0; j < 16; ++j) {
            s.x += vv[j].x; s.y += vv[j].y; s.z += vv[j].z; s.w += vv[j].w;
            c.x += (vv[j].x != 0.f) ? 1.f : 0.f;
            c.y += (vv[j].y != 0.f) ? 1.f : 0.f;
            c.z += (vv[j].z != 0.f) ? 1.f : 0.f;
            c.w += (vv[j].w != 0.f) ? 1.f : 0.f;
        }
    }
    s_s[seg][col] = s;
    s_c[seg][col] = c;
    __syncthreads();

    if (t < 192) {
        const int lane = t & 31;
        const int wid  = t >> 5;

        float4 ss = s_s[0][t], cc = s_c[0][t];
        #pragma unroll
        for (int g = 1; g < 4; ++g) {
            float4 ps = s_s[g][t], pc = s_c[g][t];
            ss.x += ps.x; ss.y += ps.y; ss.z += ps.z; ss.w += ps.w;
            cc.x += pc.x; cc.y += pc.y; cc.z += pc.z; cc.w += pc.w;
        }
        float4 avg = make_float4(ss.x / cc.x, ss.y / cc.y, ss.z / cc.z, ss.w / cc.w);
        float4 pv  = ((const float4*)pooled)[b * HV + t];

        #pragma unroll
        for (int n = 0; n < NLAB; ++n) {
            float4 w0 = ((const float4*)(Wd + n * 2 * HH))[t];
            float4 w1 = ((const float4*)(Wd + n * 2 * HH + HH))[t];
            float x = pv.x * w0.x + pv.y * w0.y + pv.z * w0.z + pv.w * w0.w
                    + avg.x * w1.x + avg.y * w1.y + avg.z * w1.z + avg.w * w1.w;
            #pragma unroll
            for (int off = 16; off; off >>= 1)
                x += __shfl_xor_sync(0xFFFFFFFFu, x, off);
            if (lane == 0) wred[wid][n] = x;
        }
    }
    __syncthreads();
    if (t < NLAB) {
        float tot = bd[t];
        #pragma unroll
        for (int w = 0; w < 6; ++w) tot += wred[w][t];
        out[b * NLAB + t] = tot;
    }
}

extern "C" void kernel_launch(void* const* d_in, const int* in_sizes, int n_in,
                              void* d_out, int out_size) {
    const float* seq    = (const float*)d_in[0];
    const float* pooled = (const float*)d_in[1];
    const float* Wk     = (const float*)d_in[2];
    const float* Wv     = (const float*)d_in[3];
    const float* Wd     = (const float*)d_in[4];
    const float* bd     = (const float*)d_in[5];
    const int*   valid  = (const int*)d_in[6];
    const int*   kvidx  = (const int*)d_in[7];
    const int*   feat   = (const int*)d_in[8];
    const int*   posm   = (const int*)d_in[9];
    const int*   asp    = (const int*)d_in[10];

    gemm_k<<<BB * NKT * NQC, 256>>>(seq, Wk, valid, kvidx, asp);
    attn2_k<<<BB * LL, 192>>>(Wv, valid, feat, posm, asp);
    reduce_head_k<<<BB, 768>>>(pooled, Wd, bd, (float*)d_out);
}